// round 7
// baseline (speedup 1.0000x reference)
#include <cuda_runtime.h>

// out[i,j] = hA[i] + hB[j] + 1 - 0.5 * sum_d s*lg2(s),  s = a + b (raw sum),
// using sum_d m*lg2(m) = 0.5*sum_d s*lg2(s) - 1 (rows normalized).
// Hybrid log2: per 8-element micro-tile, 6 logs on MUFU.LG2 (scalar) and 2 logs
// on the FMA pipe via packed f32x2 degree-8 polynomial -> MUFU and FMA pipes
// co-saturated instead of MUFU-only.

static constexpr int Dc = 512;
static constexpr int TM = 32;
static constexpr int TN = 32;
static constexpr int KB = 32;
static constexpr int LDA = 36;
static constexpr int NCHUNK = Dc / KB;  // 16

__device__ float g_hA[1024];
__device__ float g_hB[1024];

// ---------------- helpers -------------------------------------------------
__device__ __forceinline__ unsigned long long pk2(float x, float y) {
    unsigned long long r;
    asm("mov.b64 %0, {%1, %2};" : "=l"(r)
        : "r"(__float_as_uint(x)), "r"(__float_as_uint(y)));
    return r;
}
__device__ __forceinline__ unsigned long long pk2i(unsigned x, unsigned y) {
    unsigned long long r;
    asm("mov.b64 %0, {%1, %2};" : "=l"(r) : "r"(x), "r"(y));
    return r;
}

// ---------------- row half-entropy precompute -----------------------------
__global__ __launch_bounds__(128)
void row_entropy_kernel(const float* __restrict__ A, const float* __restrict__ B,
                        int nA) {
    const int row = blockIdx.x;
    const bool isA = row < nA;
    const int r = isA ? row : row - nA;
    const float* src = isA ? A : B;
    const int t = threadIdx.x;

    float4 v = reinterpret_cast<const float4*>(src + (size_t)r * Dc)[t];
    float s = 0.5f * v.x * __log2f(v.x)
            + 0.5f * v.y * __log2f(v.y)
            + 0.5f * v.z * __log2f(v.z)
            + 0.5f * v.w * __log2f(v.w);

    __shared__ float red[128];
    red[t] = s;
    __syncthreads();
    #pragma unroll
    for (int off = 64; off > 0; off >>= 1) {
        if (t < off) red[t] += red[t + off];
        __syncthreads();
    }
    if (t == 0) {
        if (isA) g_hA[r] = red[0]; else g_hB[r] = red[0];
    }
}

// ---------------- main pairwise kernel ------------------------------------
__global__ __launch_bounds__(128, 5)
void jsd_main(const float* __restrict__ A, const float* __restrict__ B,
              float* __restrict__ out, int M) {
    __shared__ float As[2][KB][LDA];
    __shared__ float Bs[2][KB][LDA];

    const int tid = threadIdx.x;
    const int tx = tid & 7;
    const int ty = tid >> 3;
    const int i0 = blockIdx.y * TM;
    const int j0 = blockIdx.x * TN;

    const int sd = tid & 31;
    const int sw = tid >> 5;
    const float* pA = A + (size_t)(i0 + sw) * Dc + sd;
    const float* pB = B + (size_t)(j0 + sw) * Dc + sd;
    float* stA = &As[0][sd][sw];
    float* stB = &Bs[0][sd][sw];
    const int BUFSZ = KB * LDA;

    // packed polynomial constants (lg2(s) = e + c0 + c1 w + ... + c8 w^8,
    // w = (2/3)*mant - 1, e from exponent bits via magic float)
    const unsigned long long C23  = pk2(0.66666667f, 0.66666667f);
    const unsigned long long NEG1 = pk2(-1.0f, -1.0f);
    const unsigned long long KNEG = pk2(-8388735.0f, -8388735.0f); // -(2^23+127)
    unsigned long long P[9];
    P[0] = pk2(0.58496250f, 0.58496250f);     // log2(3/2)
    P[1] = pk2(1.44269504f, 1.44269504f);     // +1/(1 ln2)
    P[2] = pk2(-0.72134752f, -0.72134752f);   // -1/(2 ln2)
    P[3] = pk2(0.48089835f, 0.48089835f);
    P[4] = pk2(-0.36067376f, -0.36067376f);
    P[5] = pk2(0.28853901f, 0.28853901f);
    P[6] = pk2(-0.24044917f, -0.24044917f);
    P[7] = pk2(0.20609929f, 0.20609929f);
    P[8] = pk2(-0.18033688f, -0.18033688f);

    // accumulators: 6 scalar (MUFU-routed) + 1 packed pair (poly-routed (u0,v2),(u0,v3))
    float acc00 = 0.f, acc01 = 0.f;
    float acc10 = 0.f, acc11 = 0.f, acc12 = 0.f, acc13 = 0.f;
    unsigned long long accP = 0ull;   // (0.f, 0.f)

    float ra[8], rb[8];
    #pragma unroll
    for (int e = 0; e < 8; ++e) { ra[e] = pA[e * 4 * Dc]; rb[e] = pB[e * 4 * Dc]; }
    #pragma unroll
    for (int e = 0; e < 8; ++e) { stA[e * 4] = ra[e]; stB[e * 4] = rb[e]; }
    __syncthreads();

    #pragma unroll 1
    for (int c = 0; c < NCHUNK; ++c) {
        const int p = c & 1;

        if (c + 1 < NCHUNK) {
            const float* qA = pA + (c + 1) * KB;
            const float* qB = pB + (c + 1) * KB;
            #pragma unroll
            for (int e = 0; e < 8; ++e) { ra[e] = qA[e * 4 * Dc]; rb[e] = qB[e * 4 * Dc]; }
        }

        #pragma unroll 4
        for (int d = 0; d < KB; ++d) {
            float2 a2 = *reinterpret_cast<const float2*>(&As[p][d][ty * 2]);
            float4 b4 = *reinterpret_cast<const float4*>(&Bs[p][d][tx * 4]);

            // ---- MUFU path: 6 elements -------------------------------------
            {
                float s;
                s = a2.x + b4.x; acc00 = __fmaf_rn(s, __log2f(s), acc00);
                s = a2.x + b4.y; acc01 = __fmaf_rn(s, __log2f(s), acc01);
                s = a2.y + b4.x; acc10 = __fmaf_rn(s, __log2f(s), acc10);
                s = a2.y + b4.y; acc11 = __fmaf_rn(s, __log2f(s), acc11);
                s = a2.y + b4.z; acc12 = __fmaf_rn(s, __log2f(s), acc12);
                s = a2.y + b4.w; acc13 = __fmaf_rn(s, __log2f(s), acc13);
            }

            // ---- poly path: elements (u=0,v=2),(u=0,v=3), packed f32x2 -----
            {
                unsigned long long aB = pk2(a2.x, a2.x);
                unsigned long long bH = pk2(b4.z, b4.w);
                unsigned long long s2;
                asm("add.rn.f32x2 %0, %1, %2;" : "=l"(s2) : "l"(aB), "l"(bH));
                unsigned s0u, s1u;
                asm("mov.b64 {%0, %1}, %2;" : "=r"(s0u), "=r"(s1u) : "l"(s2));
                unsigned m0 = (s0u & 0x7FFFFFu) | 0x3F800000u;   // mantissa in [1,2)
                unsigned m1 = (s1u & 0x7FFFFFu) | 0x3F800000u;
                unsigned y0 = (s0u >> 23) + 0x4B000000u;          // 2^23 + ebias
                unsigned y1 = (s1u >> 23) + 0x4B000000u;
                unsigned long long f2 = pk2i(m0, m1);
                unsigned long long y2 = pk2i(y0, y1);
                unsigned long long e2, w2;
                asm("add.rn.f32x2 %0, %1, %2;" : "=l"(e2) : "l"(y2), "l"(KNEG));
                asm("fma.rn.f32x2 %0, %1, %2, %3;"
                    : "=l"(w2) : "l"(f2), "l"(C23), "l"(NEG1));   // w = (2/3)f - 1
                unsigned long long h = P[8];
                #pragma unroll
                for (int k = 7; k >= 0; --k)
                    asm("fma.rn.f32x2 %0, %0, %1, %2;" : "+l"(h) : "l"(w2), "l"(P[k]));
                unsigned long long r2;
                asm("add.rn.f32x2 %0, %1, %2;" : "=l"(r2) : "l"(h), "l"(e2)); // lg2(s)
                asm("fma.rn.f32x2 %0, %1, %2, %0;" : "+l"(accP) : "l"(s2), "l"(r2));
            }
        }

        if (c + 1 < NCHUNK) {
            float* wA = stA + (1 - p) * BUFSZ;
            float* wB = stB + (1 - p) * BUFSZ;
            #pragma unroll
            for (int e = 0; e < 8; ++e) { wA[e * 4] = ra[e]; wB[e * 4] = rb[e]; }
        }
        __syncthreads();
    }

    // ---- epilogue: out = (hA + hB + 1) - 0.5*acc ---------------------------
    unsigned pLo, pHi;
    asm("mov.b64 {%0, %1}, %2;" : "=r"(pLo), "=r"(pHi) : "l"(accP));
    float accArr[2][4] = {
        {acc00, acc01, __uint_as_float(pLo), __uint_as_float(pHi)},
        {acc10, acc11, acc12, acc13}
    };

    float4 hb = *reinterpret_cast<const float4*>(&g_hB[j0 + tx * 4]);
    float hbv[4] = {hb.x, hb.y, hb.z, hb.w};
    #pragma unroll
    for (int u = 0; u < 2; ++u) {
        float ha1 = g_hA[i0 + ty * 2 + u] + 1.0f;
        float4 o;
        o.x = __fmaf_rn(-0.5f, accArr[u][0], ha1 + hbv[0]);
        o.y = __fmaf_rn(-0.5f, accArr[u][1], ha1 + hbv[1]);
        o.z = __fmaf_rn(-0.5f, accArr[u][2], ha1 + hbv[2]);
        o.w = __fmaf_rn(-0.5f, accArr[u][3], ha1 + hbv[3]);
        *reinterpret_cast<float4*>(
            &out[(size_t)(i0 + ty * 2 + u) * M + (j0 + tx * 4)]) = o;
    }
}

extern "C" void kernel_launch(void* const* d_in, const int* in_sizes, int n_in,
                              void* d_out, int out_size) {
    const float* A = (const float*)d_in[0];
    const float* B = (const float*)d_in[1];
    float* out = (float*)d_out;
    const int N = in_sizes[0] / Dc;   // 1024
    const int M = in_sizes[1] / Dc;   // 1024

    row_entropy_kernel<<<N + M, 128>>>(A, B, N);

    dim3 grid(M / TN, N / TM);
    jsd_main<<<grid, 128>>>(A, B, out, M);
}

// round 8
// speedup vs baseline: 1.1406x; 1.1406x over previous
#include <cuda_runtime.h>

// out[i,j] = hA[i] + hB[j] + 1 - 0.5 * sum_d s*lg2(s),  s = a + b (raw sum),
// using sum_d m*lg2(m) = 0.5*sum_d s*lg2(s) - 1 (rows normalized).
// Split-D: SPLIT blocks per output tile, combined with RED.ADD.F32 onto an
// output buffer pre-initialized to hA[i]+hB[j]+1.

static constexpr int Dc = 512;
static constexpr int TM = 32;
static constexpr int TN = 32;
static constexpr int KB = 32;
static constexpr int LDA = 36;           // floats/row; keeps float4 alignment
static constexpr int SPLIT = 2;
static constexpr int DPART = Dc / SPLIT; // 256
static constexpr int NCHUNK = DPART / KB;// 8

__device__ float g_hA[1024];
__device__ float g_hB[1024];

// ---------------- row half-entropy precompute ---------------------------
__global__ __launch_bounds__(128)
void row_entropy_kernel(const float* __restrict__ A, const float* __restrict__ B,
                        int nA) {
    const int row = blockIdx.x;
    const bool isA = row < nA;
    const int r = isA ? row : row - nA;
    const float* src = isA ? A : B;
    const int t = threadIdx.x;

    float4 v = reinterpret_cast<const float4*>(src + (size_t)r * Dc)[t];
    float s = 0.5f * v.x * __log2f(v.x)
            + 0.5f * v.y * __log2f(v.y)
            + 0.5f * v.z * __log2f(v.z)
            + 0.5f * v.w * __log2f(v.w);

    __shared__ float red[128];
    red[t] = s;
    __syncthreads();
    #pragma unroll
    for (int off = 64; off > 0; off >>= 1) {
        if (t < off) red[t] += red[t + off];
        __syncthreads();
    }
    if (t == 0) {
        if (isA) g_hA[r] = red[0]; else g_hB[r] = red[0];
    }
}

// ---------------- output init: out[i,j] = hA[i] + hB[j] + 1 -------------
__global__ __launch_bounds__(256)
void init_out_kernel(float* __restrict__ out, int M) {
    const int i = blockIdx.x;
    const int j = threadIdx.x * 4;
    const float ha1 = g_hA[i] + 1.0f;
    float4 hb = *reinterpret_cast<const float4*>(&g_hB[j]);
    float4 o = make_float4(ha1 + hb.x, ha1 + hb.y, ha1 + hb.z, ha1 + hb.w);
    *reinterpret_cast<float4*>(&out[(size_t)i * M + j]) = o;
}

// ---------------- main pairwise kernel (one D-partition per block) -------
__global__ __launch_bounds__(128, 8)
void jsd_main(const float* __restrict__ A, const float* __restrict__ B,
              float* __restrict__ out, int M) {
    __shared__ float As[KB][LDA];   // As[d][r] = a[i0+r][d0+k0+d] (raw)
    __shared__ float Bs[KB][LDA];

    const int tid = threadIdx.x;
    const int tx = tid & 7;          // 8 col-groups of 4
    const int ty = tid >> 3;         // 16 row-groups of 2
    const int i0 = blockIdx.y * TM;
    const int j0 = blockIdx.x * TN;
    const int d0 = blockIdx.z * DPART;

    // staging decomposition: d = tid&31 (fixed), r = e*4 + (tid>>5)
    const int sd = tid & 31;
    const int sw = tid >> 5;
    const float* pA = A + (size_t)(i0 + sw) * Dc + d0 + sd;
    const float* pB = B + (size_t)(j0 + sw) * Dc + d0 + sd;
    float* stA = &As[sd][sw];
    float* stB = &Bs[sd][sw];

    float acc00 = 0.f, acc01 = 0.f, acc02 = 0.f, acc03 = 0.f;
    float acc10 = 0.f, acc11 = 0.f, acc12 = 0.f, acc13 = 0.f;

    #pragma unroll 1
    for (int c = 0; c < NCHUNK; ++c) {
        const float* qA = pA + c * KB;
        const float* qB = pB + c * KB;
        #pragma unroll
        for (int e = 0; e < 8; ++e) {
            stA[e * 4] = qA[e * 4 * Dc];
            stB[e * 4] = qB[e * 4 * Dc];
        }
        __syncthreads();

        #pragma unroll 8
        for (int d = 0; d < KB; ++d) {
            float2 a2 = *reinterpret_cast<const float2*>(&As[d][ty * 2]);
            float4 b4 = *reinterpret_cast<const float4*>(&Bs[d][tx * 4]);
            float s;
            s = a2.x + b4.x; acc00 = __fmaf_rn(s, __log2f(s), acc00);
            s = a2.x + b4.y; acc01 = __fmaf_rn(s, __log2f(s), acc01);
            s = a2.x + b4.z; acc02 = __fmaf_rn(s, __log2f(s), acc02);
            s = a2.x + b4.w; acc03 = __fmaf_rn(s, __log2f(s), acc03);
            s = a2.y + b4.x; acc10 = __fmaf_rn(s, __log2f(s), acc10);
            s = a2.y + b4.y; acc11 = __fmaf_rn(s, __log2f(s), acc11);
            s = a2.y + b4.z; acc12 = __fmaf_rn(s, __log2f(s), acc12);
            s = a2.y + b4.w; acc13 = __fmaf_rn(s, __log2f(s), acc13);
        }
        __syncthreads();
    }

    // epilogue: out[i,j] -= 0.5 * acc   (RED.ADD.F32, per-pair-unique addrs)
    float* o0 = &out[(size_t)(i0 + ty * 2) * M + (j0 + tx * 4)];
    atomicAdd(o0 + 0, -0.5f * acc00);
    atomicAdd(o0 + 1, -0.5f * acc01);
    atomicAdd(o0 + 2, -0.5f * acc02);
    atomicAdd(o0 + 3, -0.5f * acc03);
    float* o1 = o0 + M;
    atomicAdd(o1 + 0, -0.5f * acc10);
    atomicAdd(o1 + 1, -0.5f * acc11);
    atomicAdd(o1 + 2, -0.5f * acc12);
    atomicAdd(o1 + 3, -0.5f * acc13);
}

extern "C" void kernel_launch(void* const* d_in, const int* in_sizes, int n_in,
                              void* d_out, int out_size) {
    const float* A = (const float*)d_in[0];
    const float* B = (const float*)d_in[1];
    float* out = (float*)d_out;
    const int N = in_sizes[0] / Dc;   // 1024
    const int M = in_sizes[1] / Dc;   // 1024

    row_entropy_kernel<<<N + M, 128>>>(A, B, N);
    init_out_kernel<<<N, 256>>>(out, M);

    dim3 grid(M / TN, N / TM, SPLIT); // 32 x 32 x 2 = 2048 blocks
    jsd_main<<<grid, 128>>>(A, B, out, M);
}

// round 9
// speedup vs baseline: 1.1996x; 1.0518x over previous
#include <cuda_runtime.h>

// out[i,j] = hA[i] + hB[j] + 1 - 0.5 * sum_d s*lg2(s),  s = a + b (raw sum),
// using sum_d m*lg2(m) = 0.5*sum_d s*lg2(s) - 1 (rows normalized).
// Split-D: SPLIT blocks per output tile combine via RED.ADD.F32 onto an output
// pre-initialized to hA[i]+hB[j]+1. Inner loop = FADD + MUFU.LG2 + FFMA per
// element (MUFU pipe is the hardware floor).

static constexpr int Dc = 512;
static constexpr int TM = 32;
static constexpr int TN = 32;
static constexpr int KB = 64;            // K-chunk (one barrier pair per chunk)
static constexpr int LDA = 36;           // smem row pad (floats)
static constexpr int SPLIT = 4;
static constexpr int DPART = Dc / SPLIT; // 128
static constexpr int NCHUNK = DPART / KB;// 2

__device__ float g_hA[1024];
__device__ float g_hB[1024];

// ---------------- row half-entropy precompute (shuffle reduction) --------
__global__ __launch_bounds__(128)
void row_entropy_kernel(const float* __restrict__ A, const float* __restrict__ B,
                        int nA) {
    const int row = blockIdx.x;
    const bool isA = row < nA;
    const int r = isA ? row : row - nA;
    const float* src = isA ? A : B;
    const int t = threadIdx.x;

    float4 v = reinterpret_cast<const float4*>(src + (size_t)r * Dc)[t];
    float s = 0.5f * v.x * __log2f(v.x)
            + 0.5f * v.y * __log2f(v.y)
            + 0.5f * v.z * __log2f(v.z)
            + 0.5f * v.w * __log2f(v.w);

    // intra-warp butterfly
    #pragma unroll
    for (int off = 16; off > 0; off >>= 1)
        s += __shfl_xor_sync(0xFFFFFFFFu, s, off);

    __shared__ float wsum[4];
    if ((t & 31) == 0) wsum[t >> 5] = s;
    __syncthreads();
    if (t == 0) {
        float tot = wsum[0] + wsum[1] + wsum[2] + wsum[3];
        if (isA) g_hA[r] = tot; else g_hB[r] = tot;
    }
}

// ---------------- output init: out[i,j] = hA[i] + hB[j] + 1 --------------
__global__ __launch_bounds__(256)
void init_out_kernel(float* __restrict__ out, int M) {
    const int i = blockIdx.x;
    const int j = threadIdx.x * 4;
    const float ha1 = g_hA[i] + 1.0f;
    float4 hb = *reinterpret_cast<const float4*>(&g_hB[j]);
    float4 o = make_float4(ha1 + hb.x, ha1 + hb.y, ha1 + hb.z, ha1 + hb.w);
    *reinterpret_cast<float4*>(&out[(size_t)i * M + j]) = o;
}

// ---------------- main pairwise kernel (one D-partition per block) -------
__global__ __launch_bounds__(128, 8)
void jsd_main(const float* __restrict__ A, const float* __restrict__ B,
              float* __restrict__ out, int M) {
    __shared__ float As[KB][LDA];   // As[d][r] = a[i0+r][d0 + c*KB + d] (raw)
    __shared__ float Bs[KB][LDA];

    const int tid = threadIdx.x;
    const int tx = tid & 7;          // 8 col-groups of 4
    const int ty = tid >> 3;         // 16 row-groups of 2
    const int i0 = blockIdx.y * TM;
    const int j0 = blockIdx.x * TN;
    const int d0 = blockIdx.z * DPART;

    // staging decomposition: d = tid&63 (fixed), r = e*2 + (tid>>6)
    const int sd = tid & 63;
    const int sw = tid >> 6;
    const float* pA = A + (size_t)(i0 + sw) * Dc + d0 + sd;
    const float* pB = B + (size_t)(j0 + sw) * Dc + d0 + sd;
    float* stA = &As[sd][sw];
    float* stB = &Bs[sd][sw];

    float acc00 = 0.f, acc01 = 0.f, acc02 = 0.f, acc03 = 0.f;
    float acc10 = 0.f, acc11 = 0.f, acc12 = 0.f, acc13 = 0.f;

    #pragma unroll 1
    for (int c = 0; c < NCHUNK; ++c) {
        const float* qA = pA + c * KB;
        const float* qB = pB + c * KB;
        #pragma unroll
        for (int e = 0; e < 16; ++e) {           // 32 rows / 2 per thread-group
            stA[e * 2] = qA[e * 2 * Dc];
            stB[e * 2] = qB[e * 2 * Dc];
        }
        __syncthreads();

        #pragma unroll 8
        for (int d = 0; d < KB; ++d) {
            float2 a2 = *reinterpret_cast<const float2*>(&As[d][ty * 2]);
            float4 b4 = *reinterpret_cast<const float4*>(&Bs[d][tx * 4]);
            float s;
            s = a2.x + b4.x; acc00 = __fmaf_rn(s, __log2f(s), acc00);
            s = a2.x + b4.y; acc01 = __fmaf_rn(s, __log2f(s), acc01);
            s = a2.x + b4.z; acc02 = __fmaf_rn(s, __log2f(s), acc02);
            s = a2.x + b4.w; acc03 = __fmaf_rn(s, __log2f(s), acc03);
            s = a2.y + b4.x; acc10 = __fmaf_rn(s, __log2f(s), acc10);
            s = a2.y + b4.y; acc11 = __fmaf_rn(s, __log2f(s), acc11);
            s = a2.y + b4.z; acc12 = __fmaf_rn(s, __log2f(s), acc12);
            s = a2.y + b4.w; acc13 = __fmaf_rn(s, __log2f(s), acc13);
        }
        __syncthreads();
    }

    // epilogue: out[i,j] -= 0.5 * acc   (RED.ADD.F32, per-pair-unique addrs)
    float* o0 = &out[(size_t)(i0 + ty * 2) * M + (j0 + tx * 4)];
    atomicAdd(o0 + 0, -0.5f * acc00);
    atomicAdd(o0 + 1, -0.5f * acc01);
    atomicAdd(o0 + 2, -0.5f * acc02);
    atomicAdd(o0 + 3, -0.5f * acc03);
    float* o1 = o0 + M;
    atomicAdd(o1 + 0, -0.5f * acc10);
    atomicAdd(o1 + 1, -0.5f * acc11);
    atomicAdd(o1 + 2, -0.5f * acc12);
    atomicAdd(o1 + 3, -0.5f * acc13);
}

extern "C" void kernel_launch(void* const* d_in, const int* in_sizes, int n_in,
                              void* d_out, int out_size) {
    const float* A = (const float*)d_in[0];
    const float* B = (const float*)d_in[1];
    float* out = (float*)d_out;
    const int N = in_sizes[0] / Dc;   // 1024
    const int M = in_sizes[1] / Dc;   // 1024

    row_entropy_kernel<<<N + M, 128>>>(A, B, N);
    init_out_kernel<<<N, 256>>>(out, M);

    dim3 grid(M / TN, N / TM, SPLIT); // 32 x 32 x 4 = 4096 blocks
    jsd_main<<<grid, 128>>>(A, B, out, M);
}

// round 10
// speedup vs baseline: 1.2150x; 1.0128x over previous
#include <cuda_runtime.h>

// out[i,j] = hA[i] + hB[j] + 1 - 0.5 * sum_d s*lg2(s),  s = a + b (raw sum),
// using sum_d m*lg2(m) = 0.5*sum_d s*lg2(s) - 1 (rows normalized).
// Split-D: 8 blocks per output tile combine via RED.ADD.F32 onto an output
// pre-initialized to hA[i]+hB[j]+1. Inner loop = FADD + MUFU.LG2 + FFMA per
// element; the MUFU pipe (rt 8/SMSP) is the hardware floor.

static constexpr int Dc = 512;
static constexpr int TM = 32;
static constexpr int TN = 32;
static constexpr int KB = 64;            // == DPART: single chunk per block
static constexpr int LDA = 36;           // smem row pad (floats)
static constexpr int SPLIT = 8;
static constexpr int DPART = Dc / SPLIT; // 64

__device__ float g_hA[1024];
__device__ float g_hB[1024];

// ---------------- row half-entropy: one warp per row, MLP=4 --------------
__global__ __launch_bounds__(128)
void row_entropy_kernel(const float* __restrict__ A, const float* __restrict__ B,
                        int nA) {
    const int warp = threadIdx.x >> 5;
    const int lane = threadIdx.x & 31;
    const int row = blockIdx.x * 4 + warp;          // 0 .. nA+nB-1
    const bool isA = row < nA;
    const int r = isA ? row : row - nA;
    const float* src = isA ? A : B;
    const float4* p = reinterpret_cast<const float4*>(src + (size_t)r * Dc);

    float4 v[4];
    #pragma unroll
    for (int e = 0; e < 4; ++e) v[e] = p[lane + e * 32];   // 4 LDG.128 in flight

    float s = 0.0f;
    #pragma unroll
    for (int e = 0; e < 4; ++e) {
        s += 0.5f * v[e].x * __log2f(v[e].x)
           + 0.5f * v[e].y * __log2f(v[e].y)
           + 0.5f * v[e].z * __log2f(v[e].z)
           + 0.5f * v[e].w * __log2f(v[e].w);
    }
    #pragma unroll
    for (int off = 16; off > 0; off >>= 1)
        s += __shfl_xor_sync(0xFFFFFFFFu, s, off);

    if (lane == 0) {
        if (isA) g_hA[r] = s; else g_hB[r] = s;
    }
}

// ---------------- output init: out[i,j] = hA[i] + hB[j] + 1 --------------
__global__ __launch_bounds__(256)
void init_out_kernel(float* __restrict__ out, int M) {
    const int i = blockIdx.x;
    const int j = threadIdx.x * 4;
    const float ha1 = g_hA[i] + 1.0f;
    float4 hb = *reinterpret_cast<const float4*>(&g_hB[j]);
    float4 o = make_float4(ha1 + hb.x, ha1 + hb.y, ha1 + hb.z, ha1 + hb.w);
    *reinterpret_cast<float4*>(&out[(size_t)i * M + j]) = o;
}

// ---------------- main pairwise kernel (one 64-wide D-slice per block) ---
__global__ __launch_bounds__(128, 8)
void jsd_main(const float* __restrict__ A, const float* __restrict__ B,
              float* __restrict__ out, int M) {
    __shared__ float As[KB][LDA];   // As[d][r] = a[i0+r][d0+d] (raw)
    __shared__ float Bs[KB][LDA];

    const int tid = threadIdx.x;
    const int tx = tid & 7;          // 8 col-groups of 4
    const int ty = tid >> 3;         // 16 row-groups of 2
    const int i0 = blockIdx.y * TM;
    const int j0 = blockIdx.x * TN;
    const int d0 = blockIdx.z * DPART;

    // staging: d = tid&63 (fixed), r = e*2 + (tid>>6)
    const int sd = tid & 63;
    const int sw = tid >> 6;
    const float* pA = A + (size_t)(i0 + sw) * Dc + d0 + sd;
    const float* pB = B + (size_t)(j0 + sw) * Dc + d0 + sd;
    float* stA = &As[sd][sw];
    float* stB = &Bs[sd][sw];

    #pragma unroll
    for (int e = 0; e < 16; ++e) {            // 32 rows, 2 per thread-group
        stA[e * 2] = pA[e * 2 * Dc];
        stB[e * 2] = pB[e * 2 * Dc];
    }
    __syncthreads();

    float acc00 = 0.f, acc01 = 0.f, acc02 = 0.f, acc03 = 0.f;
    float acc10 = 0.f, acc11 = 0.f, acc12 = 0.f, acc13 = 0.f;

    #pragma unroll 8
    for (int d = 0; d < KB; ++d) {
        float2 a2 = *reinterpret_cast<const float2*>(&As[d][ty * 2]);
        float4 b4 = *reinterpret_cast<const float4*>(&Bs[d][tx * 4]);
        float s;
        s = a2.x + b4.x; acc00 = __fmaf_rn(s, __log2f(s), acc00);
        s = a2.x + b4.y; acc01 = __fmaf_rn(s, __log2f(s), acc01);
        s = a2.x + b4.z; acc02 = __fmaf_rn(s, __log2f(s), acc02);
        s = a2.x + b4.w; acc03 = __fmaf_rn(s, __log2f(s), acc03);
        s = a2.y + b4.x; acc10 = __fmaf_rn(s, __log2f(s), acc10);
        s = a2.y + b4.y; acc11 = __fmaf_rn(s, __log2f(s), acc11);
        s = a2.y + b4.z; acc12 = __fmaf_rn(s, __log2f(s), acc12);
        s = a2.y + b4.w; acc13 = __fmaf_rn(s, __log2f(s), acc13);
    }

    // epilogue: out[i,j] -= 0.5 * acc   (RED.ADD.F32, spread addresses)
    float* o0 = &out[(size_t)(i0 + ty * 2) * M + (j0 + tx * 4)];
    atomicAdd(o0 + 0, -0.5f * acc00);
    atomicAdd(o0 + 1, -0.5f * acc01);
    atomicAdd(o0 + 2, -0.5f * acc02);
    atomicAdd(o0 + 3, -0.5f * acc03);
    float* o1 = o0 + M;
    atomicAdd(o1 + 0, -0.5f * acc10);
    atomicAdd(o1 + 1, -0.5f * acc11);
    atomicAdd(o1 + 2, -0.5f * acc12);
    atomicAdd(o1 + 3, -0.5f * acc13);
}

extern "C" void kernel_launch(void* const* d_in, const int* in_sizes, int n_in,
                              void* d_out, int out_size) {
    const float* A = (const float*)d_in[0];
    const float* B = (const float*)d_in[1];
    float* out = (float*)d_out;
    const int N = in_sizes[0] / Dc;   // 1024
    const int M = in_sizes[1] / Dc;   // 1024

    row_entropy_kernel<<<(N + M) / 4, 128>>>(A, B, N);
    init_out_kernel<<<N, 256>>>(out, M);

    dim3 grid(M / TN, N / TM, SPLIT); // 32 x 32 x 8 = 8192 blocks
    jsd_main<<<grid, 128>>>(A, B, out, M);
}